// round 8
// baseline (speedup 1.0000x reference)
#include <cuda_runtime.h>

// ---------------------------------------------------------------------------
// Quantized LSTM with LAG-1 PIPELINED scale verification:
// every step is computed fully speculatively using the previous step's po2
// exponents (k1, ka[4], k3, kh); its grid reduction (8 cells + counter add)
// is fired without waiting. At the start of the next step the barrier result
// is read and verified; misses trigger a globally-uniform fixup that rewrites
// h/out (local fq for kh-miss; 1-2 synchronous grid rounds for deeper misses,
// replayed from saved pre / c(t-2) / tc / oq). Invariant: pre(t) is exact at
// verify time, so the gate extrema cells are always exact; tc/hp cells are
// exact when the predictions they consumed hit (tiered code check).
// ---------------------------------------------------------------------------

#define GB       128
#define BPB      8
#define NT       640
#define T_STEPS  1024
#define NI       10
#define NH       20
#define NG       80
#define CSTRIDE  64              // 256B between cells
#define NCELL    16              // 0-7 main, 8 kh-fix, 9-10 full-fix, 11 retry

__device__ __align__(128) unsigned g_ctr0[32];   // pipelined step counter
__device__ __align__(128) unsigned g_ctr1[32];   // fixup-round counter
__device__ unsigned g_cells[T_STEPS * NCELL * CSTRIDE];

__global__ void qlstm_init() {
    int i = blockIdx.x * blockDim.x + threadIdx.x;   // 16384 = T_STEPS*NCELL
    if (i == 0) { g_ctr0[0] = 0u; g_ctr1[0] = 0u; }
    if (i < T_STEPS * NCELL) g_cells[i * CSTRIDE] = 0u;
}

__device__ __forceinline__ unsigned mapf(float f) {
    unsigned u = __float_as_uint(f);
    return (u & 0x80000000u) ? ~u : (u | 0x80000000u);
}
__device__ __forceinline__ float unmapf(unsigned u) {
    return __uint_as_float((u & 0x80000000u) ? (u & 0x7FFFFFFFu) : ~u);
}
__device__ __forceinline__ int po2k(float m) {
    m = fmaxf(m, 1e-8f);
    int e; float f = frexpf(m, &e);
    return (f == 0.5f) ? (e - 1) : e;
}
__device__ __forceinline__ float sc(int k)    { return __uint_as_float((unsigned)(k + 120) << 23); }
__device__ __forceinline__ float scinv(int k) { return __uint_as_float((unsigned)(134 - k) << 23); }
__device__ __forceinline__ float fq1(float x, float s, float inv) {
    float q = rintf(x * inv);
    q = fminf(fmaxf(q, -128.0f), 127.0f);
    return q * s;
}
__device__ __forceinline__ float sigm(float x) { return 1.0f / (1.0f + expf(-x)); }
__device__ __forceinline__ unsigned warp_max_u(unsigned v) {
#pragma unroll
    for (int o = 16; o; o >>= 1) v = max(v, __shfl_xor_sync(0xffffffffu, v, o));
    return v;
}
__device__ __forceinline__ void red_max_rlx(unsigned* p, unsigned v) {
    asm volatile("red.relaxed.gpu.max.u32 [%0],%1;" :: "l"(p), "r"(v) : "memory");
}
__device__ __forceinline__ void red_add_rel(unsigned* p, unsigned v) {
    asm volatile("red.release.gpu.add.u32 [%0],%1;" :: "l"(p), "r"(v) : "memory");
}
__device__ __forceinline__ unsigned atom_add_acqrel(unsigned* p, unsigned v) {
    unsigned old;
    asm volatile("atom.acq_rel.gpu.add.u32 %0,[%1],%2;" : "=r"(old) : "l"(p), "r"(v) : "memory");
    return old;
}
__device__ __forceinline__ unsigned ld_acq(const unsigned* p) {
    unsigned v; asm volatile("ld.acquire.gpu.u32 %0,[%1];" : "=r"(v) : "l"(p) : "memory"); return v;
}
__device__ __forceinline__ unsigned ld_rlx(const unsigned* p) {
    unsigned v; asm volatile("ld.relaxed.gpu.u32 %0,[%1];" : "=r"(v) : "l"(p) : "memory"); return v;
}

// synchronous fixup round on g_ctr1 (rare path)
__device__ __forceinline__ unsigned grid_bar1(unsigned* cell0, unsigned myv, int ncontrib,
                                              unsigned tgt, int lane) {
    if (lane < ncontrib) red_max_rlx(cell0 + lane * CSTRIDE, myv);
    __syncwarp();
    unsigned last = 0;
    if (lane == 0) last = (atom_add_acqrel(&g_ctr1[0], 1u) == tgt - 1u) ? 1u : 0u;
    last = __shfl_sync(0xffffffffu, last, 0);
    if (!last) { while (ld_acq(&g_ctr1[0]) < tgt) { } }
    __syncwarp();
    return (lane < ncontrib) ? ld_rlx(cell0 + lane * CSTRIDE) : 0u;
}

__global__ void __launch_bounds__(NT, 1) qlstm_main(
    const float* __restrict__ x,
    const float* __restrict__ Wih,
    const float* __restrict__ Whh,
    float* __restrict__ out)
{
    __shared__ __align__(16) float sh_h[2][BPB * NH];   // double-buffered h
    __shared__ __align__(16) float sh_x[BPB * NI];
    __shared__ float               sh_act[NG * BPB];
    __shared__ unsigned            sh_red[12];
    __shared__ int                 sh_k[8];   // 0:k1 1-4:ka 5:k3 6:kh 7:code/flag

    const int tid  = threadIdx.x;
    const int g    = tid / BPB;
    const int b    = tid % BPB;
    const int gr   = tid / 160;          // warp-uniform gate group
    const int lane = tid & 31;
    const int wid  = tid >> 5;

    if (tid < 12) sh_red[tid] = 0u;
    if (tid < 8)  sh_k[tid] = 0;         // initial predictions (verified at t=1)
    if (tid < BPB * NH) { sh_h[0][tid] = 0.0f; sh_h[1][tid] = 0.0f; }
    __syncthreads();

    // ---- weight scale (block-local, once) ----
    {
        float wm = 0.0f;
        for (int k = tid; k < NG * NI; k += NT) wm = fmaxf(wm, fabsf(Wih[k]));
        for (int k = tid; k < NG * NH; k += NT) wm = fmaxf(wm, fabsf(Whh[k]));
        unsigned u = warp_max_u(__float_as_uint(wm));
        if (lane == 0) atomicMax(&sh_red[11], u);
        __syncthreads();
    }
    int kw = po2k(__uint_as_float(sh_red[11]));
    float ws = sc(kw), wsi = scinv(kw);
    __syncthreads();
    if (tid == 0) sh_red[11] = 0u;

    float wi[NI], wh[NH];
#pragma unroll
    for (int i2 = 0; i2 < NI; i2++) wi[i2] = fq1(Wih[g * NI + i2], ws, wsi);
#pragma unroll
    for (int j2 = 0; j2 < NH; j2++) wh[j2] = fq1(Whh[g * NH + j2], ws, wsi);

    // speculation history (per-thread)
    float pre_m1 = 0.0f;                             // pre(t-1), all threads
    float c_m1 = 0.0f, c_m2 = 0.0f;                  // c(t-1), c(t-2)   (tid<160)
    float tc_m1 = 0.0f, oq_m1 = 0.0f, hp_m1 = 0.0f;  // tanh(c), o_q, h_pre (tid<160)
    unsigned nbar1 = 0;

    const int sq  = tid - 560;                        // warps 17-19 stage x
    const int sxb = (sq >= 0) ? sq / NI : 0;
    const int sxi = (sq >= 0) ? sq % NI : 0;
    float xr = 0.0f;
    if (sq >= 0) {
        sh_x[sq] = x[((size_t)(blockIdx.x * BPB + sxb) * T_STEPS + 0) * NI + sxi];
        xr       = x[((size_t)(blockIdx.x * BPB + sxb) * T_STEPS + 1) * NI + sxi];
    }
    __syncthreads();

    for (int t = 0; t <= T_STEPS; ++t) {
        // =================== VERIFY step t-1 ===================
        if (t > 0) {
            if (wid == 0) {
                if (lane == 0) { while (ld_acq(&g_ctr0[0]) < (unsigned)t * GB) { } }
                __syncwarp();
                unsigned* cb = &g_cells[(size_t)(t - 1) * NCELL * CSTRIDE];
                unsigned cv = (lane < 8) ? ld_rlx(cb + lane * CSTRIDE) : 0u;
                unsigned kk = (lane < 4 || lane == 5) ? cv : 0u;
                kk = max(kk, __shfl_xor_sync(0xffffffffu, kk, 4));
                kk = max(kk, __shfl_xor_sync(0xffffffffu, kk, 2));
                kk = max(kk, __shfl_xor_sync(0xffffffffu, kk, 1));
                int k1 = po2k(unmapf(kk));
                k1 = __shfl_sync(0xffffffffu, k1, 0);
                float s1 = sc(k1), v1 = scinv(k1);
                float mng = unmapf(__shfl_sync(0xffffffffu, cv, 4));
                float myp = unmapf(cv);
                float a;
                if (lane == 2) {
                    float q1 = fq1(myp, s1, v1), q2 = fq1(-mng, s1, v1);
                    a = tanhf(fmaxf(q1, -q2));
                } else {
                    a = sigm(fq1(myp, s1, v1));
                }
                int ka  = po2k(fabsf(a));
                int k3t = po2k(__uint_as_float(__shfl_sync(0xffffffffu, cv, 6)));
                int kht = po2k(__uint_as_float(__shfl_sync(0xffffffffu, cv, 7)));
                bool okl = (lane < 4) ? (ka == sh_k[1 + lane]) : true;
                unsigned bm = __ballot_sync(0xffffffffu, okl);
                int k1p_old = sh_k[0], k3p_old = sh_k[5], khp_old = sh_k[6];
                int hit1 = (((bm & 0xFu) == 0xFu) && (k1 == k1p_old)) ? 1 : 0;
                int hit3 = (k3t == k3p_old) ? 1 : 0;
                int hith = (kht == khp_old) ? 1 : 0;
                int code = hit1 ? (hit3 ? (hith ? 0 : 1) : 2) : 3;
                if (lane < 4) sh_k[1 + lane] = ka;
                if (lane == 0) {
                    sh_k[0] = k1;
                    if (hit1) sh_k[5] = k3t;             // cell6 exact only when hit1
                    if (hit1 && hit3) sh_k[6] = kht;     // cell7 exact only when hit1&hit3
                    sh_k[7] = code;
                }
            }
            __syncthreads();                             // SBv
            const int code = sh_k[7];

            if (code == 1) {
                // kh-only miss: local h rewrite
                if (tid < 160) {
                    int kh = sh_k[6];
                    float hq = fq1(hp_m1, sc(kh), scinv(kh));
                    sh_h[(t - 1) & 1][b * NH + g] = hq;
                    out[((size_t)(blockIdx.x * BPB + b) * T_STEPS + (t - 1)) * NH + g] = hq;
                }
                __syncthreads();
            } else if (code == 2) {
                // k3 miss (k1/ka hit): redo h_pre with true k3, one grid round for kh
                int k3 = sh_k[5];
                if (tid < 160) hp_m1 = oq_m1 * fq1(tc_m1, sc(k3), scinv(k3));
                if (wid < 5) {
                    unsigned aw = warp_max_u(__float_as_uint(fabsf(hp_m1)));
                    if (lane == 0) atomicMax(&sh_red[10], aw);
                }
                __syncthreads();
                if (wid == 0) {
                    unsigned v = (lane == 0) ? sh_red[10] : 0u;
                    __syncwarp();
                    if (lane == 0) sh_red[10] = 0u;
                    nbar1++;
                    unsigned cv = grid_bar1(&g_cells[((size_t)(t - 1) * NCELL + 8) * CSTRIDE],
                                            v, 1, nbar1 * GB, lane);
                    if (lane == 0) sh_k[6] = po2k(__uint_as_float(cv));
                }
                __syncthreads();
                if (tid < 160) {
                    int kh = sh_k[6];
                    float hq = fq1(hp_m1, sc(kh), scinv(kh));
                    sh_h[(t - 1) & 1][b * NH + g] = hq;
                    out[((size_t)(blockIdx.x * BPB + b) * T_STEPS + (t - 1)) * NH + g] = hq;
                }
                __syncthreads();
            } else if (code == 3) {
                // full miss: replay step t-1 from pre_m1 / c(t-2)
                {
                    int k1 = sh_k[0], kat = sh_k[1 + gr];
                    float gq  = fq1(pre_m1, sc(k1), scinv(k1));
                    float act = (gr == 2) ? tanhf(gq) : sigm(gq);
                    sh_act[tid] = fq1(act, sc(kat), scinv(kat));
                }
                __syncthreads();
                int k3g = sh_k[5];
                if (tid < 160) {
                    float iq = sh_act[tid], ff = sh_act[tid + 160], gg = sh_act[tid + 320];
                    oq_m1 = sh_act[tid + 480];
                    c_m1  = ff * c_m2 + iq * gg;
                    tc_m1 = tanhf(c_m1);
                    hp_m1 = oq_m1 * fq1(tc_m1, sc(k3g), scinv(k3g));
                }
                if (wid < 5) {
                    unsigned a1 = warp_max_u(__float_as_uint(fabsf(tc_m1)));
                    unsigned a2 = warp_max_u(__float_as_uint(fabsf(hp_m1)));
                    if (lane == 0) { atomicMax(&sh_red[10], a1); atomicMax(&sh_red[11], a2); }
                }
                __syncthreads();
                if (wid == 0) {
                    unsigned v = (lane < 2) ? sh_red[10 + lane] : 0u;
                    __syncwarp();
                    if (lane < 2) sh_red[10 + lane] = 0u;
                    nbar1++;
                    unsigned cv = grid_bar1(&g_cells[((size_t)(t - 1) * NCELL + 9) * CSTRIDE],
                                            v, 2, nbar1 * GB, lane);
                    int kx = po2k(__uint_as_float(cv));
                    int k3 = __shfl_sync(0xffffffffu, kx, 0);
                    int kh = __shfl_sync(0xffffffffu, kx, 1);
                    if (lane == 0) {
                        sh_k[5] = k3; sh_k[6] = kh;
                        sh_k[7] = (k3 == k3g) ? 0 : 1;   // retry flag
                    }
                }
                __syncthreads();
                if (sh_k[7]) {   // k3 guess also missed: one more round
                    int k3 = sh_k[5];
                    if (tid < 160) hp_m1 = oq_m1 * fq1(tc_m1, sc(k3), scinv(k3));
                    if (wid < 5) {
                        unsigned aw = warp_max_u(__float_as_uint(fabsf(hp_m1)));
                        if (lane == 0) atomicMax(&sh_red[10], aw);
                    }
                    __syncthreads();
                    if (wid == 0) {
                        unsigned v = (lane == 0) ? sh_red[10] : 0u;
                        __syncwarp();
                        if (lane == 0) sh_red[10] = 0u;
                        nbar1++;
                        unsigned cv = grid_bar1(&g_cells[((size_t)(t - 1) * NCELL + 11) * CSTRIDE],
                                                v, 1, nbar1 * GB, lane);
                        if (lane == 0) sh_k[6] = po2k(__uint_as_float(cv));
                    }
                    __syncthreads();
                }
                if (tid < 160) {
                    int kh = sh_k[6];
                    float hq = fq1(hp_m1, sc(kh), scinv(kh));
                    sh_h[(t - 1) & 1][b * NH + g] = hq;
                    out[((size_t)(blockIdx.x * BPB + b) * T_STEPS + (t - 1)) * NH + g] = hq;
                }
                __syncthreads();
            }
        }
        if (t == T_STEPS) break;

        // =================== COMPUTE step t (fully speculative) ===================
        const int k1p = sh_k[0], kap = sh_k[1 + gr], k3p = sh_k[5], khp = sh_k[6];

        float p0 = 0.0f, p1 = 0.0f;
        {
            const float2* px = reinterpret_cast<const float2*>(&sh_x[b * NI]);
            const float2* ph = reinterpret_cast<const float2*>(&sh_h[(t + 1) & 1][b * NH]);
#pragma unroll
            for (int j = 0; j < NI / 2; j++) {
                float2 v = px[j];
                p0 = fmaf(v.x, wi[2 * j], p0); p1 = fmaf(v.y, wi[2 * j + 1], p1);
            }
#pragma unroll
            for (int j = 0; j < NH / 2; j++) {
                float2 v = ph[j];
                p0 = fmaf(v.x, wh[2 * j], p0); p1 = fmaf(v.y, wh[2 * j + 1], p1);
            }
        }
        float pre = p0 + p1;
        pre_m1 = pre;

        unsigned kp = warp_max_u(mapf(pre));
        unsigned kn = warp_max_u(mapf(-pre));
        if (lane == 0) { atomicMax(&sh_red[gr], kp); atomicMax(&sh_red[4 + gr], kn); }
        {
            float gq  = fq1(pre, sc(k1p), scinv(k1p));
            float act = (gr == 2) ? tanhf(gq) : sigm(gq);
            sh_act[tid] = fq1(act, sc(kap), scinv(kap));
        }
        __syncthreads();                                 // SC1
        if (sq >= 0 && t + 1 < T_STEPS) sh_x[sq] = xr;

        if (tid < 160) {
            float iq = sh_act[tid], ff = sh_act[tid + 160], gg = sh_act[tid + 320];
            oq_m1 = sh_act[tid + 480];
            float cn = ff * c_m1 + iq * gg;
            c_m2 = c_m1; c_m1 = cn;
            tc_m1 = tanhf(cn);
            hp_m1 = oq_m1 * fq1(tc_m1, sc(k3p), scinv(k3p));
        }
        if (wid < 5) {
            unsigned a1 = warp_max_u(__float_as_uint(fabsf(tc_m1)));
            unsigned a2 = warp_max_u(__float_as_uint(fabsf(hp_m1)));
            if (lane == 0) { atomicMax(&sh_red[8], a1); atomicMax(&sh_red[9], a2); }
        }
        if (sq >= 0 && t + 2 < T_STEPS)
            xr = x[((size_t)(blockIdx.x * BPB + sxb) * T_STEPS + (t + 2)) * NI + sxi];
        __syncthreads();                                 // SC2

        // speculative h(t) with predicted kh; fixed next iter if wrong
        if (tid < 160) {
            float hq = fq1(hp_m1, sc(khp), scinv(khp));
            sh_h[t & 1][b * NH + g] = hq;
            out[((size_t)(blockIdx.x * BPB + b) * T_STEPS + t) * NH + g] = hq;
        }

        // fire step-t reductions; DO NOT WAIT
        if (wid == 0) {
            unsigned v = (lane < 10) ? sh_red[lane] : 0u;
            __syncwarp();
            if (lane < 10) sh_red[lane] = 0u;
            unsigned n0 = __shfl_sync(0xffffffffu, v, 4);
            unsigned n1 = __shfl_sync(0xffffffffu, v, 5);
            unsigned n2 = __shfl_sync(0xffffffffu, v, 6);
            unsigned n3 = __shfl_sync(0xffffffffu, v, 7);
            unsigned t8 = __shfl_sync(0xffffffffu, v, 8);
            unsigned t9 = __shfl_sync(0xffffffffu, v, 9);
            unsigned myv = v;
            if (lane == 4) myv = n2;
            if (lane == 5) myv = max(max(n0, n1), max(n2, n3));
            if (lane == 6) myv = t8;
            if (lane == 7) myv = t9;
            unsigned* cb = &g_cells[(size_t)t * NCELL * CSTRIDE];
            if (lane < 8) red_max_rlx(cb + lane * CSTRIDE, myv);
            __syncwarp();
            if (lane == 0) red_add_rel(&g_ctr0[0], 1u);
        }
        // no block-wide sync needed: sh_h/sh_red next touched after SBv(t+1)
    }
}

extern "C" void kernel_launch(void* const* d_in, const int* in_sizes, int n_in,
                              void* d_out, int out_size) {
    (void)in_sizes; (void)n_in; (void)out_size;
    qlstm_init<<<32, 512>>>();
    qlstm_main<<<GB, NT>>>((const float*)d_in[0],
                           (const float*)d_in[1],
                           (const float*)d_in[2],
                           (float*)d_out);
}